// round 13
// baseline (speedup 1.0000x reference)
#include <cuda_runtime.h>
#include <cuda_fp16.h>
#include <math.h>
#include <stdint.h>

// Problem dims (fixed by the dataset)
#define BSZ 4
#define LSZ 2048
#define DSZ 512
#define MROWS (BSZ * LSZ)   // 8192

// Scan chunking
#define NC 64               // chunks along L
#define LC (LSZ / NC)       // 32 steps per chunk

// GEMM tiling
#define BM 128
#define BN 256
#define BK 32
#define NCHUNK (DSZ / BK)   // 16

// smem rows: 32 halves (64B data) padded to 80B -> conflict-free ldmatrix
#define ROWW 20
#define ROWB 80
#define A_MATB (BM * ROWB)               // 10240 B  (A hi or lo)
#define W_MATB (BN * ROWB)               // 20480 B  (W hi or lo)
#define OFF_AHI 0
#define OFF_ALO A_MATB
#define OFF_WHI (2 * A_MATB)
#define OFF_WLO (2 * A_MATB + W_MATB)
#define STAGEB  (2 * A_MATB + 2 * W_MATB)   // 61440 B
#define GEMM_SMEM (2 * STAGEB)              // 122880 B

#define SCAN_SMEM (LC * DSZ * 4)            // 64KB h tile for fused LN

// ---------------------------------------------------------------------------
// Scratch (static device globals; no runtime allocation allowed)
// ---------------------------------------------------------------------------
__device__ float    g_angle[MROWS * DSZ];
__device__ uint32_t g_wh[DSZ * DSZ / 2];   // half2-packed hi of W
__device__ uint32_t g_wl[DSZ * DSZ / 2];   // half2-packed lo of W
__device__ float2   g_P[BSZ * NC * DSZ];
__device__ float2   g_E[BSZ * NC * DSZ];

// ---------------------------------------------------------------------------
// helpers (baseline sm_80+ PTX only; harness compiles via compute_100)
// ---------------------------------------------------------------------------
__device__ __forceinline__ uint32_t smem_u32(const void* p) {
    uint32_t a;
    asm("{ .reg .u64 t; cvta.to.shared.u64 t, %1; cvt.u32.u64 %0, t; }" : "=r"(a) : "l"(p));
    return a;
}

__device__ __forceinline__ void split2(float x, float y, uint32_t& hi, uint32_t& lo) {
    __half2 h = __floats2half2_rn(x, y);
    float2 hf = __half22float2(h);
    __half2 l = __floats2half2_rn(x - hf.x, y - hf.y);
    hi = *reinterpret_cast<uint32_t*>(&h);
    lo = *reinterpret_cast<uint32_t*>(&l);
}

// D += A * B (m16n8k16 fp16, fp32 accum). NOT volatile: pure register op.
__device__ __forceinline__ void mma16(float* d, const uint32_t* a,
                                      uint32_t b0, uint32_t b1) {
    asm("mma.sync.aligned.m16n8k16.row.col.f32.f16.f16.f32 "
        "{%0,%1,%2,%3}, {%4,%5,%6,%7}, {%8,%9}, {%0,%1,%2,%3};"
        : "+f"(d[0]), "+f"(d[1]), "+f"(d[2]), "+f"(d[3])
        : "r"(a[0]), "r"(a[1]), "r"(a[2]), "r"(a[3]), "r"(b0), "r"(b1));
}

__device__ __forceinline__ void ldm4(uint32_t* r, uint32_t addr) {
    asm volatile("ldmatrix.sync.aligned.m8n8.x4.shared.b16 {%0,%1,%2,%3}, [%4];"
        : "=r"(r[0]), "=r"(r[1]), "=r"(r[2]), "=r"(r[3]) : "r"(addr));
}

#define CPA16(dst, src) \
    asm volatile("cp.async.cg.shared.global [%0], [%1], 16;" :: "r"(dst), "l"(src))
#define CPA_COMMIT() asm volatile("cp.async.commit_group;" ::: "memory")
#define CPA_WAIT0()  asm volatile("cp.async.wait_group 0;" ::: "memory")

// ---------------------------------------------------------------------------
// Kernel 0: split W into packed half2 hi/lo arrays (1 MB; ~1 us)
// ---------------------------------------------------------------------------
#define NW8 (DSZ * DSZ / 8)

__global__ __launch_bounds__(256) void wsplit_kernel(const float* __restrict__ w)
{
    const int j = blockIdx.x * blockDim.x + threadIdx.x;
    if (j < NW8) {
        const float4* p = (const float4*)w + (size_t)j * 2;
        float4 v0 = p[0], v1 = p[1];
        uint4 H, L;
        split2(v0.x, v0.y, H.x, L.x);
        split2(v0.z, v0.w, H.y, L.y);
        split2(v1.x, v1.y, H.z, L.z);
        split2(v1.z, v1.w, H.w, L.w);
        ((uint4*)g_wh)[j] = H;
        ((uint4*)g_wl)[j] = L;
    }
}

// ---------------------------------------------------------------------------
// GEMM: angle = x @ W^T + b, split-fp16 (hi*hi + hi*lo + lo*hi), mma.sync.
// BM=128 x BN=256; 16 warps (4m x 4n), warp tile 32x64. (R11-proven)
// ---------------------------------------------------------------------------
__global__ __launch_bounds__(512, 1) void gemm_mma(
    const float* __restrict__ A, const float* __restrict__ bias)
{
    extern __shared__ char dynsm[];
    uint32_t* sm = (uint32_t*)dynsm;
    const uint32_t sb = smem_u32(dynsm);

    const int tid  = threadIdx.x;
    const int wid  = tid >> 5;
    const int lane = tid & 31;
    const int g    = lane >> 2;
    const int tg   = lane & 3;
    const int bm   = blockIdx.y * BM;
    const int bn   = blockIdx.x * BN;
    const int m0w  = (wid >> 2) * 32;
    const int n0w  = (wid & 3) * 64;

    const int lmr = lane & 15;
    const int lmk = (lane >> 4) * 16;
    uint32_t aAddr[2], bAddr[4];
#pragma unroll
    for (int mt = 0; mt < 2; mt++)
        aAddr[mt] = sb + OFF_AHI + (m0w + mt * 16 + lmr) * ROWB + lmk;
#pragma unroll
    for (int p = 0; p < 4; p++)
        bAddr[p] = sb + OFF_WHI + (n0w + p * 16 + lmr) * ROWB + lmk;

    const int srow = tid >> 2;
    const int q    = tid & 3;
    const float* Ag = A + (size_t)(bm + srow) * DSZ + q * 8;

    const char* whp = (const char*)g_wh;
    const char* wlp = (const char*)g_wl;

    float4 pa[2];
    auto ldgA = [&](int c) {
        const float* ap = Ag + c * BK;
        pa[0] = *(const float4*)(ap);
        pa[1] = *(const float4*)(ap + 4);
    };
    auto stsA = [&](int buf) {
        uint32_t* st = sm + (buf * STAGEB) / 4;
        const int base = srow * ROWW + q * 4;
        uint4 H, L;
        split2(pa[0].x, pa[0].y, H.x, L.x);
        split2(pa[0].z, pa[0].w, H.y, L.y);
        split2(pa[1].x, pa[1].y, H.z, L.z);
        split2(pa[1].z, pa[1].w, H.w, L.w);
        *(uint4*)(st + base)               = H;
        *(uint4*)(st + A_MATB / 4 + base)  = L;
    };
    auto cpW = [&](int c, int buf) {
        const uint32_t st = sb + buf * STAGEB;
#pragma unroll
        for (int k = 0; k < 2; k++) {
            const int s   = tid + k * 512;
            const int row = s >> 2, seg = (s & 3) * 16;
            const uint32_t dst = st + row * ROWB + seg;
            const size_t  src = (size_t)(bn + row) * (DSZ * 2) + c * 64 + seg;
            CPA16(dst + OFF_WHI, whp + src);
            CPA16(dst + OFF_WLO, wlp + src);
        }
        CPA_COMMIT();
    };

    float C[2][8][4];
#pragma unroll
    for (int mt = 0; mt < 2; mt++)
#pragma unroll
        for (int nt = 0; nt < 8; nt++)
#pragma unroll
            for (int j = 0; j < 4; j++) C[mt][nt][j] = 0.f;

    ldgA(0);
    cpW(0, 0);

    for (int c = 0; c < NCHUNK; c++) {
        const int buf = c & 1;
        stsA(buf);
        CPA_WAIT0();
        __syncthreads();
        if (c + 1 < NCHUNK) { ldgA(c + 1); cpW(c + 1, buf ^ 1); }

        const uint32_t boff = buf * STAGEB;
#pragma unroll
        for (int ks = 0; ks < 2; ks++) {
            const uint32_t off = boff + ks * 32;
            uint32_t ah[2][4], al[2][4];
#pragma unroll
            for (int mt = 0; mt < 2; mt++) {
                ldm4(ah[mt], aAddr[mt] + off);
                ldm4(al[mt], aAddr[mt] + off + A_MATB);
            }
#pragma unroll
            for (int p = 0; p < 4; p++) {
                uint32_t bh[4], bl[4];
                ldm4(bh, bAddr[p] + off);
                ldm4(bl, bAddr[p] + off + W_MATB);
                mma16(C[0][2 * p],     ah[0], bh[0], bh[2]);
                mma16(C[0][2 * p + 1], ah[0], bh[1], bh[3]);
                mma16(C[1][2 * p],     ah[1], bh[0], bh[2]);
                mma16(C[1][2 * p + 1], ah[1], bh[1], bh[3]);
                mma16(C[0][2 * p],     ah[0], bl[0], bl[2]);
                mma16(C[0][2 * p + 1], ah[0], bl[1], bl[3]);
                mma16(C[1][2 * p],     ah[1], bl[0], bl[2]);
                mma16(C[1][2 * p + 1], ah[1], bl[1], bl[3]);
                mma16(C[0][2 * p],     al[0], bh[0], bh[2]);
                mma16(C[0][2 * p + 1], al[0], bh[1], bh[3]);
                mma16(C[1][2 * p],     al[1], bh[0], bh[2]);
                mma16(C[1][2 * p + 1], al[1], bh[1], bh[3]);
            }
        }
    }

#pragma unroll
    for (int nt = 0; nt < 8; nt++) {
        const int col = bn + n0w + nt * 8 + 2 * tg;
        const float bz0 = bias[col], bz1 = bias[col + 1];
#pragma unroll
        for (int mt = 0; mt < 2; mt++) {
            const int row = bm + m0w + mt * 16 + g;
            float2 v0 = make_float2(C[mt][nt][0] + bz0, C[mt][nt][1] + bz1);
            float2 v1 = make_float2(C[mt][nt][2] + bz0, C[mt][nt][3] + bz1);
            *(float2*)(g_angle + (size_t)row * DSZ + col) = v0;
            *(float2*)(g_angle + (size_t)(row + 8) * DSZ + col) = v1;
        }
    }
}

// ---------------------------------------------------------------------------
// Complex linear scan:  g[t] = c[t]*g[t-1] + x[t]
// 256 threads, each owning TWO d-chains (d, d+256): 2x ILP; register
// prefetch of t+1 operands overlaps gmem latency with the serial chain.
// ---------------------------------------------------------------------------
#define EDECAY 0.999000499833375f   // expf(-0.001f)

__global__ __launch_bounds__(256) void scan_phase1(
    const float* __restrict__ x, const float* __restrict__ scale,
    const float* __restrict__ lre, const float* __restrict__ lim)
{
    const int b = blockIdx.x / NC;
    const int c = blockIdx.x % NC;
    const int d0 = threadIdx.x;

    float sc[2], lr_[2], li_[2];
#pragma unroll
    for (int u = 0; u < 2; u++) {
        sc[u]  = scale[d0 + u * 256];
        lr_[u] = lre[d0 + u * 256];
        li_[u] = lim[d0 + u * 256];
    }

    const size_t base = ((size_t)b * LSZ + (size_t)c * LC) * DSZ + d0;
    const float* ap = g_angle + base;
    const float* xp = x + base;

    float gr[2] = {0.f, 0.f}, gi[2] = {0.f, 0.f};
    float Pr[2] = {1.f, 1.f}, Pi[2] = {0.f, 0.f};
    float aC[2], xC[2];
    aC[0] = ap[0];   aC[1] = ap[256];
    xC[0] = xp[0];   xC[1] = xp[256];

#pragma unroll 4
    for (int tt = 0; tt < LC; tt++) {
        float aN[2], xN[2];
        if (tt + 1 < LC) {
            const size_t o = (size_t)(tt + 1) * DSZ;
            aN[0] = ap[o]; aN[1] = ap[o + 256];
            xN[0] = xp[o]; xN[1] = xp[o + 256];
        }
#pragma unroll
        for (int u = 0; u < 2; u++) {
            float s, co;
            __sincosf(aC[u] * sc[u], &s, &co);
            if (c == 0 && tt == 0) {
                gr[u] = xC[u] + EDECAY * (co * lr_[u] - s * li_[u]);
                gi[u] = EDECAY * (co * li_[u] + s * lr_[u]);
                // c[0] = 1 -> P unchanged
            } else {
                const float cr = EDECAY * co, ci = EDECAY * s;
                float ngr = fmaf(cr, gr[u], fmaf(-ci, gi[u], xC[u]));
                float ngi = fmaf(cr, gi[u], ci * gr[u]);
                gr[u] = ngr; gi[u] = ngi;
                float nPr = fmaf(cr, Pr[u], -ci * Pi[u]);
                float nPi = fmaf(cr, Pi[u],  ci * Pr[u]);
                Pr[u] = nPr; Pi[u] = nPi;
            }
            aC[u] = aN[u]; xC[u] = xN[u];
        }
    }

#pragma unroll
    for (int u = 0; u < 2; u++) {
        const int idx = (b * NC + c) * DSZ + d0 + u * 256;
        g_E[idx] = make_float2(gr[u], gi[u]);
        g_P[idx] = make_float2(Pr[u], Pi[u]);
    }
}

// Phase 2: 2-way d ILP scan into smem h[LC][DSZ], then per-warp LN rows.
__global__ __launch_bounds__(256) void scan_phase2_ln(
    const float* __restrict__ x, const float* __restrict__ scale,
    const float* __restrict__ lre, const float* __restrict__ lim,
    const float* __restrict__ gamma, const float* __restrict__ beta,
    float* __restrict__ y)
{
    extern __shared__ char dynsm[];
    float* hsm = (float*)dynsm;   // [LC][DSZ]

    const int b = blockIdx.x / NC;
    const int c = blockIdx.x % NC;
    const int d0 = threadIdx.x;
    const int lane = d0 & 31, w = d0 >> 5;   // 8 warps

    float sc[2], lr_[2], li_[2];
#pragma unroll
    for (int u = 0; u < 2; u++) {
        sc[u]  = scale[d0 + u * 256];
        lr_[u] = lre[d0 + u * 256];
        li_[u] = lim[d0 + u * 256];
    }

    // carry fold (both chains)
    float gr[2] = {0.f, 0.f}, gi[2] = {0.f, 0.f};
    for (int j = 0; j < c; j++) {
#pragma unroll
        for (int u = 0; u < 2; u++) {
            const int idx = (b * NC + j) * DSZ + d0 + u * 256;
            const float2 P = g_P[idx];
            const float2 E = g_E[idx];
            float ngr = fmaf(P.x, gr[u], fmaf(-P.y, gi[u], E.x));
            float ngi = fmaf(P.x, gi[u], fmaf( P.y, gr[u], E.y));
            gr[u] = ngr; gi[u] = ngi;
        }
    }

    const size_t base = ((size_t)b * LSZ + (size_t)c * LC) * DSZ + d0;
    const float* ap = g_angle + base;
    const float* xp = x + base;

    float aC[2], xC[2];
    aC[0] = ap[0];   aC[1] = ap[256];
    xC[0] = xp[0];   xC[1] = xp[256];

#pragma unroll 4
    for (int tt = 0; tt < LC; tt++) {
        float aN[2], xN[2];
        if (tt + 1 < LC) {
            const size_t o = (size_t)(tt + 1) * DSZ;
            aN[0] = ap[o]; aN[1] = ap[o + 256];
            xN[0] = xp[o]; xN[1] = xp[o + 256];
        }
#pragma unroll
        for (int u = 0; u < 2; u++) {
            float s, co;
            __sincosf(aC[u] * sc[u], &s, &co);
            if (c == 0 && tt == 0) {
                gr[u] = xC[u] + EDECAY * (co * lr_[u] - s * li_[u]);
                gi[u] = EDECAY * (co * li_[u] + s * lr_[u]);
            } else {
                const float cr = EDECAY * co, ci = EDECAY * s;
                float ngr = fmaf(cr, gr[u], fmaf(-ci, gi[u], xC[u]));
                float ngi = fmaf(cr, gi[u], ci * gr[u]);
                gr[u] = ngr; gi[u] = ngi;
            }
            hsm[tt * DSZ + d0 + u * 256] = gr[u];
            aC[u] = aN[u]; xC[u] = xN[u];
        }
    }
    __syncthreads();

    // LN: 8 warps; warp w handles rows w, w+8, w+16, w+24.
    float4 g4[4], b4[4];
#pragma unroll
    for (int j = 0; j < 4; j++) {
        g4[j] = ((const float4*)gamma)[lane + j * 32];
        b4[j] = ((const float4*)beta)[lane + j * 32];
    }
    float* yrowbase = y + ((size_t)b * LSZ + (size_t)c * LC) * DSZ;

#pragma unroll
    for (int rr = w; rr < LC; rr += 8) {
        const float4* hp = (const float4*)(hsm + rr * DSZ);
        float4 v[4];
        float s = 0.f, ss = 0.f;
#pragma unroll
        for (int j = 0; j < 4; j++) {
            v[j] = hp[lane + j * 32];
            s  += v[j].x + v[j].y + v[j].z + v[j].w;
            ss += v[j].x * v[j].x + v[j].y * v[j].y
                + v[j].z * v[j].z + v[j].w * v[j].w;
        }
#pragma unroll
        for (int o = 16; o > 0; o >>= 1) {
            s  += __shfl_xor_sync(0xffffffffu, s,  o);
            ss += __shfl_xor_sync(0xffffffffu, ss, o);
        }
        const float mu   = s * (1.0f / DSZ);
        const float var  = ss * (1.0f / DSZ) - mu * mu;
        const float rstd = rsqrtf(var + 1e-5f);

        float4* yp = (float4*)(yrowbase + (size_t)rr * DSZ);
#pragma unroll
        for (int j = 0; j < 4; j++) {
            float4 o;
            o.x = (v[j].x - mu) * rstd * g4[j].x + b4[j].x;
            o.y = (v[j].y - mu) * rstd * g4[j].y + b4[j].y;
            o.z = (v[j].z - mu) * rstd * g4[j].z + b4[j].z;
            o.w = (v[j].w - mu) * rstd * g4[j].w + b4[j].w;
            yp[lane + j * 32] = o;
        }
    }
}

// ---------------------------------------------------------------------------
// Launch
// ---------------------------------------------------------------------------
extern "C" void kernel_launch(void* const* d_in, const int* in_sizes, int n_in,
                              void* d_out, int out_size)
{
    const float* x     = (const float*)d_in[0];
    const float* fc_w  = (const float*)d_in[1];
    const float* fc_b  = (const float*)d_in[2];
    const float* scale = (const float*)d_in[3];
    const float* lre   = (const float*)d_in[4];
    const float* lim   = (const float*)d_in[5];
    const float* gamma = (const float*)d_in[6];
    const float* beta  = (const float*)d_in[7];
    float* y = (float*)d_out;

    cudaFuncSetAttribute(gemm_mma, cudaFuncAttributeMaxDynamicSharedMemorySize,
                         GEMM_SMEM);
    cudaFuncSetAttribute(scan_phase2_ln, cudaFuncAttributeMaxDynamicSharedMemorySize,
                         SCAN_SMEM);

    wsplit_kernel<<<(NW8 + 255) / 256, 256>>>(fc_w);

    dim3 ggrid(DSZ / BN, MROWS / BM);   // (2, 64) = 128 CTAs
    gemm_mma<<<ggrid, 512, GEMM_SMEM>>>(x, fc_b);

    scan_phase1<<<BSZ * NC, 256>>>(x, scale, lre, lim);
    scan_phase2_ln<<<BSZ * NC, 256, SCAN_SMEM>>>(x, scale, lre, lim, gamma, beta, y);
}